// round 15
// baseline (speedup 1.0000x reference)
#include <cuda_runtime.h>
#include <cuda_fp16.h>
#include <cstdint>

#define Bsz  128
#define Tseq 512
#define Din  512
#define Hdim 1024
#define BH   (Bsz * Hdim)
#define TBH  ((size_t)Tseq * (size_t)Bsz * (size_t)Hdim)
#define NC   128
#define RNT  256           // rec threads (8 warps)
#define Mrows 65536        // B*T

// ---------------- static device scratch ----------------
__device__ float g_xproj[3ULL * 512ULL * 128ULL * 1024ULL]; // (gate, t, b, h)
__device__ float g_h[BH];                 // h fp32, [b][k]
__device__ float g_z[BH];                 // z gate fp32, [b][n]
__device__ uint32_t g_hF [2][4][64][32][4];   // h  A-fragments [bhalf][mtile][kk][lane][reg]
__device__ uint32_t g_rhF[2][4][64][32][4];   // r*h A-fragments
__device__ uint32_t g_xh[(size_t)Mrows * (Din / 2)];   // x fp16 packed pairs (proj A)
__device__ uint32_t g_WzrS[256][64][32][2];     // rec B-frags fp16 single
__device__ uint32_t g_WhhS[128][64][32][2];
__device__ uint32_t g_WpF2[2][384][8][32][8];   // proj B-frags fp16 hi/lo
__device__ unsigned int g_bar = 0;

// ---------------- helpers ----------------
__device__ __forceinline__ float sigmoidf_(float x) { return 1.0f / (1.0f + __expf(-x)); }

__device__ __forceinline__ void hsplit(float v, __half& hi, __half& lo) {
    hi = __float2half_rn(v);
    lo = __float2half_rn(v - __half2float(hi));
}
__device__ __forceinline__ uint32_t packh(__half a, __half b) {
    __half2 h2 = __halves2half2(a, b);
    return *(uint32_t*)&h2;
}

// fragment slot for value-pair (b, j), j even: matches mma.m16n8k16 A layout
__device__ __forceinline__ uint32_t* fragAddr(uint32_t (*F)[4][64][32][4], int b, int j) {
    int bhalf = b >> 6, brow = b & 63, mt = brow >> 4, rr = brow & 15;
    int kk = j >> 4, ccl = j & 15;
    int lane = (rr & 7) * 4 + ((ccl & 7) >> 1);
    int reg = (rr >> 3) + 2 * (ccl >> 3);
    return &F[bhalf][mt][kk][lane][reg];
}

__device__ __forceinline__ void cp16(uint32_t s, const void* g) {
    asm volatile("cp.async.cg.shared.global [%0], [%1], 16;" :: "r"(s), "l"(g));
}
#define CP_COMMIT() asm volatile("cp.async.commit_group;")
#define CP_WAIT0()  asm volatile("cp.async.wait_group 0;")
#define CP_WAIT1()  asm volatile("cp.async.wait_group 1;")
#define CP_WAIT2()  asm volatile("cp.async.wait_group 2;")

__device__ __forceinline__ unsigned grid_arrive() {
    unsigned old;
    asm volatile("atom.release.gpu.global.add.u32 %0, [%1], 1;"
                 : "=r"(old) : "l"(&g_bar) : "memory");
    return (old / NC + 1u) * NC;
}
__device__ __forceinline__ void grid_wait(unsigned target) {
    unsigned v;
    do {
        asm volatile("ld.acquire.gpu.global.u32 %0, [%1];"
                     : "=r"(v) : "l"(&g_bar) : "memory");
    } while (v < target);
}
__device__ __forceinline__ void grid_sync() {
    __syncthreads();
    if (threadIdx.x == 0) grid_wait(grid_arrive());
    __syncthreads();
}

__device__ __forceinline__ void ldsm4(uint32_t (&r)[4], uint32_t a) {
    asm volatile("ldmatrix.sync.aligned.m8n8.x4.shared.b16 {%0,%1,%2,%3}, [%4];"
                 : "=r"(r[0]), "=r"(r[1]), "=r"(r[2]), "=r"(r[3]) : "r"(a));
}
__device__ __forceinline__ void mma_hf(float (&d)[4], const uint32_t (&a)[4],
                                       uint32_t b0, uint32_t b1) {
    asm volatile(
        "mma.sync.aligned.m16n8k16.row.col.f32.f16.f16.f32 "
        "{%0,%1,%2,%3}, {%4,%5,%6,%7}, {%8,%9}, {%0,%1,%2,%3};"
        : "+f"(d[0]), "+f"(d[1]), "+f"(d[2]), "+f"(d[3])
        : "r"(a[0]), "r"(a[1]), "r"(a[2]), "r"(a[3]), "r"(b0), "r"(b1));
}

// ---------------- merged setup kernels (2 launches) ----------------
__global__ void setup_x_kernel(const float* __restrict__ x, const float* __restrict__ h0) {
    size_t i = (size_t)blockIdx.x * 256 + threadIdx.x;   // Mrows*Din/2
    float2 v = *(const float2*)&x[i * 2];
    g_xh[i] = packh(__float2half_rn(v.x), __float2half_rn(v.y));
    if (i < BH / 2) {
        int b = (int)(i >> 9), kp = (int)(i & 511);
        float2 h2 = *(const float2*)&h0[(size_t)b * Hdim + kp * 2];
        *(float2*)&g_h[(size_t)b * Hdim + kp * 2] = h2;
        *fragAddr(g_hF, b, kp * 2) = packh(__float2half_rn(h2.x), __float2half_rn(h2.y));
    }
}

__global__ void setup_W_kernel(const float* __restrict__ Wiu, const float* __restrict__ Wir,
                               const float* __restrict__ Wih, const float* __restrict__ Whu,
                               const float* __restrict__ Whr, const float* __restrict__ Whh) {
    int i = blockIdx.x * 256 + threadIdx.x;
    if (i < 786432) {                                   // proj B-frags (hi/lo)
        int e = i & 7, lane = (i >> 3) & 31, kc = (i >> 8) & 7, nt = i >> 11;
        int kl = e >> 1, reg = e & 1;
        int n = nt * 8 + (lane >> 2);
        int gate = n >> 10, nn = n & (Hdim - 1);
        const float* W = (gate == 0) ? Wiu : (gate == 1 ? Wir : Wih);
        int k = kc * 64 + kl * 16 + reg * 8 + (lane & 3) * 2;
        float v0 = W[(size_t)k * Hdim + nn];
        float v1 = W[(size_t)(k + 1) * Hdim + nn];
        __half h0a, l0a, h1a, l1a;
        hsplit(v0, h0a, l0a); hsplit(v1, h1a, l1a);
        g_WpF2[0][nt][kc][lane][e] = packh(h0a, h1a);
        g_WpF2[1][nt][kc][lane][e] = packh(l0a, l1a);
    } else if (i < 786432 + 1048576) {                  // Wzr single fp16
        int u = i - 786432;
        int reg = u & 1, lane = (u >> 1) & 31, k16 = (u >> 6) & 63, nt = u >> 12;
        int n = nt * 8 + (lane >> 2);
        int k = k16 * 16 + reg * 8 + (lane & 3) * 2;
        const float* W = (n < Hdim) ? Whu : Whr;
        int nn = n & (Hdim - 1);
        g_WzrS[nt][k16][lane][reg] =
            packh(__float2half_rn(W[(size_t)k * Hdim + nn]),
                  __float2half_rn(W[(size_t)(k + 1) * Hdim + nn]));
    } else {                                            // Whh single fp16
        int u = i - 786432 - 1048576;
        int reg = u & 1, lane = (u >> 1) & 31, k16 = (u >> 6) & 63, nt = u >> 12;
        int n = nt * 8 + (lane >> 2);
        int k = k16 * 16 + reg * 8 + (lane & 3) * 2;
        g_WhhS[nt][k16][lane][reg] =
            packh(__float2half_rn(Whh[(size_t)k * Hdim + n]),
                  __float2half_rn(Whh[(size_t)(k + 1) * Hdim + n]));
    }
}

// ---------------- phase A: tensor-core proj (fp16 A-single / B hi+lo, 2-pass) ----------------
#define PROJ_SMEM (3 * 16384)
__global__ void __launch_bounds__(256) proj_mma_kernel(
    const float* __restrict__ bu, const float* __restrict__ br, const float* __restrict__ bh)
{
    extern __shared__ char sm[];
    const uint32_t smb = (uint32_t)__cvta_generic_to_shared(sm);
    const int tid = threadIdx.x, wid = tid >> 5, lane = tid & 31;
    const int gid = lane >> 2, t4 = lane & 3;
    const int mw = wid & 3, nw = wid >> 2;
    const int rb = blockIdx.x * 128, cb = blockIdx.y * 128;
    const int gate = cb >> 10;
    const float* bias = (gate == 0) ? bu : (gate == 1 ? br : bh);

    const int lrowoff = ((lane >> 3) & 1) * 8 + (lane & 7);
    const int lkq = lane >> 4;
    const int lsw = (lane & 7) * 16;

    float acc[2][8][4];
#pragma unroll
    for (int mt = 0; mt < 2; mt++)
#pragma unroll
        for (int nt = 0; nt < 8; nt++)
#pragma unroll
            for (int i = 0; i < 4; i++) acc[mt][nt][i] = 0.f;

    auto load_chunk = [&](int st, int kc) {
#pragma unroll
        for (int q = 0; q < 4; q++) {
            int u = tid + q * 256;          // 0..1023
            int row = u >> 3, cu = u & 7;
            uint32_t dst = smb + st * 16384 + row * 128
                         + ((cu * 16) ^ ((row & 7) * 16));
            cp16(dst, g_xh + (size_t)(rb + row) * 256 + kc * 32 + cu * 4);
        }
        CP_COMMIT();
    };

    load_chunk(0, 0); load_chunk(1, 1); load_chunk(2, 2);
    for (int c = 0; c < 8; c++) {
        if (c <= 5)      CP_WAIT2();
        else if (c == 6) CP_WAIT1();
        else             CP_WAIT0();
        __syncthreads();
        const uint32_t base = smb + (c % 3) * 16384;
#pragma unroll
        for (int kl = 0; kl < 4; kl++) {
            const uint32_t bcol = (uint32_t)((kl * 32 + lkq * 16) ^ lsw);
            uint32_t Ah[2][4];
#pragma unroll
            for (int mt = 0; mt < 2; mt++) {
                const int mtile = mw * 2 + mt;
                ldsm4(Ah[mt], base + (uint32_t)((mtile * 16 + lrowoff) * 128) + bcol);
            }
#pragma unroll
            for (int nt = 0; nt < 8; nt++) {
                const int ntile = blockIdx.y * 16 + nw * 8 + nt;
                unsigned long long bhp = *(const unsigned long long*)&g_WpF2[0][ntile][c][lane][kl * 2];
                unsigned long long blp = *(const unsigned long long*)&g_WpF2[1][ntile][c][lane][kl * 2];
                const uint32_t bh0 = (uint32_t)bhp, bh1 = (uint32_t)(bhp >> 32);
                const uint32_t bl0 = (uint32_t)blp, bl1 = (uint32_t)(blp >> 32);
#pragma unroll
                for (int mt = 0; mt < 2; mt++) {
                    mma_hf(acc[mt][nt], Ah[mt], bh0, bh1);
                    mma_hf(acc[mt][nt], Ah[mt], bl0, bl1);
                }
            }
        }
        __syncthreads();
        if (c + 3 < 8) load_chunk(c % 3, c + 3);
    }

    float* gout = g_xproj + (size_t)gate * TBH;
#pragma unroll
    for (int nt = 0; nt < 8; nt++) {
        const int ncol = cb + nw * 64 + nt * 8 + t4 * 2;
        const int nn = ncol & (Hdim - 1);
        const float2 bv = *(const float2*)&bias[nn];
#pragma unroll
        for (int mt = 0; mt < 2; mt++) {
#pragma unroll
            for (int hf = 0; hf < 2; hf++) {
                const int m = rb + mw * 32 + mt * 16 + gid + hf * 8;
                const int t = m & (Tseq - 1), bb = m >> 9;
                float2 v;
                v.x = acc[mt][nt][hf * 2]     + bv.x;
                v.y = acc[mt][nt][hf * 2 + 1] + bv.y;
                *(float2*)&gout[((size_t)(t * Bsz + bb)) * Hdim + nn] = v;
            }
        }
    }
}

// ---------------- persistent recurrence: register-direct A frags, depth-4 prefetch ----------------
// smem: [0,65536) Wzr frags | [65536,98304) Whh frags | [98304,106496) PART reduction
#define REC_SMEM 106496
__global__ void __launch_bounds__(RNT, 1) gru_rec_kernel(float* __restrict__ out)
{
    extern __shared__ char sm[];
    const uint32_t smb = (uint32_t)__cvta_generic_to_shared(sm);
    float* PART = (float*)(sm + 98304);

    const int tid  = threadIdx.x, cta = blockIdx.x;
    const int wid  = tid >> 5, lane = tid & 31;
    const int gid  = lane >> 2, t4 = lane & 3;
    const int bhalf = cta & 1, bbase = bhalf * 64;
    const int ngrp  = cta >> 1;            // 0..63
    const int isR   = ngrp >= 32;

    // 8 warps = 4 mtiles (mw) x 2 k-slices (ks: odd/even kk)
    const int mw = wid & 3, ks = wid >> 2;

    // ---- preload this CTA's weight fragments into smem (once) ----
    {
        const char* s1 = (const char*)g_WzrS + (size_t)(ngrp * 4) * 16384;
#pragma unroll
        for (int q = 0; q < 16; q++)
            cp16(smb + (uint32_t)(tid + q * RNT) * 16, s1 + (size_t)(tid + q * RNT) * 16);
        const char* s2 = (const char*)g_WhhS + (size_t)(ngrp * 2) * 16384;
#pragma unroll
        for (int q = 0; q < 8; q++)
            cp16(smb + 65536 + (uint32_t)(tid + q * RNT) * 16, s2 + (size_t)(tid + q * RNT) * 16);
        CP_COMMIT();
        CP_WAIT0();
        __syncthreads();
    }

    const uint32_t* hFw  = &g_hF [bhalf][mw][0][0][0];   // [64][32][4]
    const uint32_t* rhFw = &g_rhF[bhalf][mw][0][0][0];

    for (int t = 0; t < Tseq; t++) {
        // ================= phase 1 : z / r (n-slice = 32 cols) =================
        float acc[4][4];
#pragma unroll
        for (int nt = 0; nt < 4; nt++)
#pragma unroll
            for (int i = 0; i < 4; i++) acc[nt][i] = 0.f;

        const int Ncol0 = ngrp * 32 + t4 * 2;           // + nt*8
        const int jj0 = isR ? (Ncol0 - Hdim) : Ncol0;
        float2 pxg[4][2], ph2[4][2];
        if (ks == 0) {
            const float* xg = g_xproj + (isR ? TBH : (size_t)0) + (size_t)t * BH;
#pragma unroll
            for (int nt = 0; nt < 4; nt++)
#pragma unroll
                for (int hf = 0; hf < 2; hf++) {
                    const int b = bbase + mw * 16 + gid + hf * 8;
                    pxg[nt][hf] = __ldcs((const float2*)(xg + (size_t)b * Hdim + jj0 + nt * 8));
                    if (isR) ph2[nt][hf] = __ldcg((const float2*)&g_h[(size_t)b * Hdim + jj0 + nt * 8]);
                }
        }

        // MMA loop, depth-4 register prefetch on the A-fragment LDG stream
        {
            uint4 Abuf[4];
#pragma unroll
            for (int p = 0; p < 4; p++)
                Abuf[p] = __ldcg((const uint4*)(hFw + (size_t)(p * 2 + ks) * 128 + lane * 4));
#pragma unroll 4
            for (int j = 0; j < 32; j++) {
                uint32_t A[4] = { Abuf[j & 3].x, Abuf[j & 3].y, Abuf[j & 3].z, Abuf[j & 3].w };
                if (j + 4 < 32)
                    Abuf[j & 3] = __ldcg((const uint4*)(hFw + (size_t)((j + 4) * 2 + ks) * 128 + lane * 4));
                const int kk = j * 2 + ks;
#pragma unroll
                for (int nt = 0; nt < 4; nt++) {
                    const uint2 Bv = *(const uint2*)(sm + (size_t)(nt * 16384 + kk * 256 + lane * 8));
                    mma_hf(acc[nt], A, Bv.x, Bv.y);
                }
            }
        }

        // cross-k reduction (ks1 -> ks0)
        if (ks == 1) {
#pragma unroll
            for (int nt = 0; nt < 4; nt++)
#pragma unroll
                for (int i = 0; i < 4; i++)
                    PART[(mw * 32 + lane) * 16 + nt * 4 + i] = acc[nt][i];
        }
        __syncthreads();
        if (ks == 0) {
#pragma unroll
            for (int nt = 0; nt < 4; nt++)
#pragma unroll
                for (int i = 0; i < 4; i++)
                    acc[nt][i] += PART[(mw * 32 + lane) * 16 + nt * 4 + i];

            // phase1 epilogue
            if (!isR) {
#pragma unroll
                for (int nt = 0; nt < 4; nt++)
#pragma unroll
                    for (int hf = 0; hf < 2; hf++) {
                        const int b = bbase + mw * 16 + gid + hf * 8;
                        float2 zv;
                        zv.x = sigmoidf_(acc[nt][hf * 2]     + pxg[nt][hf].x);
                        zv.y = sigmoidf_(acc[nt][hf * 2 + 1] + pxg[nt][hf].y);
                        *(float2*)&g_z[(size_t)b * Hdim + Ncol0 + nt * 8] = zv;
                    }
            } else {
                // coalesced fragment stores: 2 x uint4 per thread
#pragma unroll
                for (int q = 0; q < 2; q++) {
                    uint32_t v[4];
#pragma unroll
                    for (int m = 0; m < 2; m++) {        // nt = 2q + m
                        const int nt = 2 * q + m;
#pragma unroll
                        for (int hf = 0; hf < 2; hf++) {
                            float r0 = sigmoidf_(acc[nt][hf * 2]     + pxg[nt][hf].x) * ph2[nt][hf].x;
                            float r1 = sigmoidf_(acc[nt][hf * 2 + 1] + pxg[nt][hf].y) * ph2[nt][hf].y;
                            v[hf + 2 * m] = packh(__float2half_rn(r0), __float2half_rn(r1));
                        }
                    }
                    const int kkq = (ngrp - 32) * 2 + q;
                    *(uint4*)&g_rhF[bhalf][mw][kkq][lane][0] =
                        make_uint4(v[0], v[1], v[2], v[3]);
                }
            }
        }
        grid_sync();

        // ================= phase 2 : candidate + update (n-slice = 16 cols) =================
        float ac2[2][4];
#pragma unroll
        for (int nt = 0; nt < 2; nt++)
#pragma unroll
            for (int i = 0; i < 4; i++) ac2[nt][i] = 0.f;

        const int n0 = ngrp * 16 + t4 * 2;              // + nt*8
        float2 pxh[2][2], pz2[2][2], phv[2][2];
        if (ks == 0) {
            const float* xh = g_xproj + 2 * TBH + (size_t)t * BH;
#pragma unroll
            for (int nt = 0; nt < 2; nt++)
#pragma unroll
                for (int hf = 0; hf < 2; hf++) {
                    const int b = bbase + mw * 16 + gid + hf * 8;
                    pxh[nt][hf] = __ldcs((const float2*)(xh + (size_t)b * Hdim + n0 + nt * 8));
                    pz2[nt][hf] = __ldcg((const float2*)&g_z[(size_t)b * Hdim + n0 + nt * 8]);
                    phv[nt][hf] = __ldcg((const float2*)&g_h[(size_t)b * Hdim + n0 + nt * 8]);
                }
        }

        {
            uint4 Abuf[4];
#pragma unroll
            for (int p = 0; p < 4; p++)
                Abuf[p] = __ldcg((const uint4*)(rhFw + (size_t)(p * 2 + ks) * 128 + lane * 4));
#pragma unroll 4
            for (int j = 0; j < 32; j++) {
                uint32_t A[4] = { Abuf[j & 3].x, Abuf[j & 3].y, Abuf[j & 3].z, Abuf[j & 3].w };
                if (j + 4 < 32)
                    Abuf[j & 3] = __ldcg((const uint4*)(rhFw + (size_t)((j + 4) * 2 + ks) * 128 + lane * 4));
                const int kk = j * 2 + ks;
#pragma unroll
                for (int nt = 0; nt < 2; nt++) {
                    const uint2 Bv = *(const uint2*)(sm + (size_t)(65536 + nt * 16384 + kk * 256 + lane * 8));
                    mma_hf(ac2[nt], A, Bv.x, Bv.y);
                }
            }
        }

        if (ks == 1) {
#pragma unroll
            for (int nt = 0; nt < 2; nt++)
#pragma unroll
                for (int i = 0; i < 4; i++)
                    PART[(mw * 32 + lane) * 8 + nt * 4 + i] = ac2[nt][i];
        }
        __syncthreads();

        float hn[2][2][2];
        if (ks == 0) {
#pragma unroll
            for (int nt = 0; nt < 2; nt++)
#pragma unroll
                for (int i = 0; i < 4; i++)
                    ac2[nt][i] += PART[(mw * 32 + lane) * 8 + nt * 4 + i];

            // phase2 epilogue: h update; ONE coalesced uint4 fragment store per thread
            uint32_t v[4];
#pragma unroll
            for (int nt = 0; nt < 2; nt++) {
#pragma unroll
                for (int hf = 0; hf < 2; hf++) {
                    const int b = bbase + mw * 16 + gid + hf * 8;
                    const int n = n0 + nt * 8;
                    float c0 = tanhf(ac2[nt][hf * 2]     + pxh[nt][hf].x);
                    float c1 = tanhf(ac2[nt][hf * 2 + 1] + pxh[nt][hf].y);
                    hn[nt][hf][0] = phv[nt][hf].x + pz2[nt][hf].x * (c0 - phv[nt][hf].x);
                    hn[nt][hf][1] = phv[nt][hf].y + pz2[nt][hf].y * (c1 - phv[nt][hf].y);
                    *(float2*)&g_h[(size_t)b * Hdim + n] = make_float2(hn[nt][hf][0], hn[nt][hf][1]);
                    v[hf + 2 * nt] = packh(__float2half_rn(hn[nt][hf][0]),
                                           __float2half_rn(hn[nt][hf][1]));
                }
            }
            *(uint4*)&g_hF[bhalf][mw][ngrp][lane][0] = make_uint4(v[0], v[1], v[2], v[3]);
        }
        __syncthreads();
        unsigned target = 0;
        if (tid == 0) target = grid_arrive();
        if (out && ks == 0) {
#pragma unroll
            for (int nt = 0; nt < 2; nt++)
#pragma unroll
                for (int hf = 0; hf < 2; hf++) {
                    const int b = bbase + mw * 16 + gid + hf * 8;
                    *(float2*)&out[(size_t)t * BH + (size_t)b * Hdim + n0 + nt * 8] =
                        make_float2(hn[nt][hf][0], hn[nt][hf][1]);
                }
        }
        if (tid == 0) grid_wait(target);
        __syncthreads();
    }
}

// ---------------- final hidden state ----------------
__global__ void hlast_kernel(float* __restrict__ dst) {
    int i = blockIdx.x * 256 + threadIdx.x;
    dst[i] = g_h[i];
}

// ---------------- launch ----------------
extern "C" void kernel_launch(void* const* d_in, const int* in_sizes, int n_in,
                              void* d_out, int out_size)
{
    (void)in_sizes; (void)n_in;
    const float* x   = (const float*)d_in[0];
    const float* h0  = (const float*)d_in[1];
    const float* Wiu = (const float*)d_in[2];
    const float* Whu = (const float*)d_in[3];
    const float* bu  = (const float*)d_in[4];
    const float* Wir = (const float*)d_in[5];
    const float* Whr = (const float*)d_in[6];
    const float* br  = (const float*)d_in[7];
    const float* Wih = (const float*)d_in[8];
    const float* Whh = (const float*)d_in[9];
    const float* bh  = (const float*)d_in[10];
    float* out = (float*)d_out;

    const bool write_seq  = ((size_t)out_size >= TBH);
    const bool write_last = ((size_t)out_size >= TBH + (size_t)Bsz * Hdim);

    cudaFuncSetAttribute(proj_mma_kernel,
                         cudaFuncAttributeMaxDynamicSharedMemorySize, PROJ_SMEM);
    cudaFuncSetAttribute(gru_rec_kernel,
                         cudaFuncAttributeMaxDynamicSharedMemorySize, REC_SMEM);

    setup_x_kernel<<<65536, 256>>>(x, h0);                          // launch 0
    setup_W_kernel<<<9216, 256>>>(Wiu, Wir, Wih, Whu, Whr, Whh);    // launch 1

    dim3 pg(Mrows / 128, 3072 / 128);   // 512 x 24
    proj_mma_kernel<<<pg, 256, PROJ_SMEM>>>(bu, br, bh);            // launch 2

    gru_rec_kernel<<<NC, RNT, REC_SMEM>>>(write_seq ? out : nullptr); // launch 3 (ncu slot)

    if (write_last)        hlast_kernel<<<BH / 256, 256>>>(out + TBH);
    else if (!write_seq)   hlast_kernel<<<BH / 256, 256>>>(out);
}

// round 16
// speedup vs baseline: 1.0282x; 1.0282x over previous
#include <cuda_runtime.h>
#include <cuda_fp16.h>
#include <cstdint>

#define Bsz  128
#define Tseq 512
#define Din  512
#define Hdim 1024
#define BH   (Bsz * Hdim)
#define TBH  ((size_t)Tseq * (size_t)Bsz * (size_t)Hdim)
#define NC   128
#define RNT  512           // rec threads (16 warps)
#define Mrows 65536        // B*T

// ---------------- static device scratch ----------------
__device__ float g_xproj[3ULL * 512ULL * 128ULL * 1024ULL]; // (gate, t, b, h)
__device__ float g_h[BH];                 // h fp32, [b][k]
__device__ float g_z[BH];                 // z gate fp32, [b][n]
__device__ uint32_t g_hF [2][4][64][32][4];   // h  A-fragments [bhalf][mtile][kk][lane][reg]
__device__ uint32_t g_rhF[2][4][64][32][4];   // r*h A-fragments
__device__ uint32_t g_xh[(size_t)Mrows * (Din / 2)];   // x fp16 packed pairs (proj A)
__device__ uint32_t g_WzrS[256][64][32][2];     // rec B-frags fp16 single
__device__ uint32_t g_WhhS[128][64][32][2];
__device__ uint32_t g_WpF2[2][384][8][32][8];   // proj B-frags fp16 hi/lo
__device__ unsigned int g_bar = 0;

// ---------------- helpers ----------------
__device__ __forceinline__ float sigmoidf_(float x) { return 1.0f / (1.0f + __expf(-x)); }

__device__ __forceinline__ void hsplit(float v, __half& hi, __half& lo) {
    hi = __float2half_rn(v);
    lo = __float2half_rn(v - __half2float(hi));
}
__device__ __forceinline__ uint32_t packh(__half a, __half b) {
    __half2 h2 = __halves2half2(a, b);
    return *(uint32_t*)&h2;
}

// fragment slot for value-pair (b, j), j even: matches mma.m16n8k16 A layout
__device__ __forceinline__ uint32_t* fragAddr(uint32_t (*F)[4][64][32][4], int b, int j) {
    int bhalf = b >> 6, brow = b & 63, mt = brow >> 4, rr = brow & 15;
    int kk = j >> 4, ccl = j & 15;
    int lane = (rr & 7) * 4 + ((ccl & 7) >> 1);
    int reg = (rr >> 3) + 2 * (ccl >> 3);
    return &F[bhalf][mt][kk][lane][reg];
}

__device__ __forceinline__ void cp16(uint32_t s, const void* g) {
    asm volatile("cp.async.cg.shared.global [%0], [%1], 16;" :: "r"(s), "l"(g));
}
#define CP_COMMIT() asm volatile("cp.async.commit_group;")
#define CP_WAIT0()  asm volatile("cp.async.wait_group 0;")
#define CP_WAIT1()  asm volatile("cp.async.wait_group 1;")
#define CP_WAIT2()  asm volatile("cp.async.wait_group 2;")

__device__ __forceinline__ unsigned grid_arrive() {
    unsigned old;
    asm volatile("atom.release.gpu.global.add.u32 %0, [%1], 1;"
                 : "=r"(old) : "l"(&g_bar) : "memory");
    return (old / NC + 1u) * NC;
}
__device__ __forceinline__ void grid_wait(unsigned target) {
    unsigned v;
    do {
        asm volatile("ld.acquire.gpu.global.u32 %0, [%1];"
                     : "=r"(v) : "l"(&g_bar) : "memory");
    } while (v < target);
}
__device__ __forceinline__ void grid_sync() {
    __syncthreads();
    if (threadIdx.x == 0) grid_wait(grid_arrive());
    __syncthreads();
}

__device__ __forceinline__ void ldsm4(uint32_t (&r)[4], uint32_t a) {
    asm volatile("ldmatrix.sync.aligned.m8n8.x4.shared.b16 {%0,%1,%2,%3}, [%4];"
                 : "=r"(r[0]), "=r"(r[1]), "=r"(r[2]), "=r"(r[3]) : "r"(a));
}
__device__ __forceinline__ void mma_hf(float (&d)[4], const uint32_t (&a)[4],
                                       uint32_t b0, uint32_t b1) {
    asm volatile(
        "mma.sync.aligned.m16n8k16.row.col.f32.f16.f16.f32 "
        "{%0,%1,%2,%3}, {%4,%5,%6,%7}, {%8,%9}, {%0,%1,%2,%3};"
        : "+f"(d[0]), "+f"(d[1]), "+f"(d[2]), "+f"(d[3])
        : "r"(a[0]), "r"(a[1]), "r"(a[2]), "r"(a[3]), "r"(b0), "r"(b1));
}

// ---------------- merged setup kernels (2 launches) ----------------
__global__ void setup_x_kernel(const float* __restrict__ x, const float* __restrict__ h0) {
    size_t i = (size_t)blockIdx.x * 256 + threadIdx.x;   // Mrows*Din/2
    float2 v = *(const float2*)&x[i * 2];
    g_xh[i] = packh(__float2half_rn(v.x), __float2half_rn(v.y));
    if (i < BH / 2) {
        int b = (int)(i >> 9), kp = (int)(i & 511);
        float2 h2 = *(const float2*)&h0[(size_t)b * Hdim + kp * 2];
        *(float2*)&g_h[(size_t)b * Hdim + kp * 2] = h2;
        *fragAddr(g_hF, b, kp * 2) = packh(__float2half_rn(h2.x), __float2half_rn(h2.y));
    }
}

__global__ void setup_W_kernel(const float* __restrict__ Wiu, const float* __restrict__ Wir,
                               const float* __restrict__ Wih, const float* __restrict__ Whu,
                               const float* __restrict__ Whr, const float* __restrict__ Whh) {
    int i = blockIdx.x * 256 + threadIdx.x;
    if (i < 786432) {                                   // proj B-frags (hi/lo)
        int e = i & 7, lane = (i >> 3) & 31, kc = (i >> 8) & 7, nt = i >> 11;
        int kl = e >> 1, reg = e & 1;
        int n = nt * 8 + (lane >> 2);
        int gate = n >> 10, nn = n & (Hdim - 1);
        const float* W = (gate == 0) ? Wiu : (gate == 1 ? Wir : Wih);
        int k = kc * 64 + kl * 16 + reg * 8 + (lane & 3) * 2;
        float v0 = W[(size_t)k * Hdim + nn];
        float v1 = W[(size_t)(k + 1) * Hdim + nn];
        __half h0a, l0a, h1a, l1a;
        hsplit(v0, h0a, l0a); hsplit(v1, h1a, l1a);
        g_WpF2[0][nt][kc][lane][e] = packh(h0a, h1a);
        g_WpF2[1][nt][kc][lane][e] = packh(l0a, l1a);
    } else if (i < 786432 + 1048576) {                  // Wzr single fp16
        int u = i - 786432;
        int reg = u & 1, lane = (u >> 1) & 31, k16 = (u >> 6) & 63, nt = u >> 12;
        int n = nt * 8 + (lane >> 2);
        int k = k16 * 16 + reg * 8 + (lane & 3) * 2;
        const float* W = (n < Hdim) ? Whu : Whr;
        int nn = n & (Hdim - 1);
        g_WzrS[nt][k16][lane][reg] =
            packh(__float2half_rn(W[(size_t)k * Hdim + nn]),
                  __float2half_rn(W[(size_t)(k + 1) * Hdim + nn]));
    } else {                                            // Whh single fp16
        int u = i - 786432 - 1048576;
        int reg = u & 1, lane = (u >> 1) & 31, k16 = (u >> 6) & 63, nt = u >> 12;
        int n = nt * 8 + (lane >> 2);
        int k = k16 * 16 + reg * 8 + (lane & 3) * 2;
        g_WhhS[nt][k16][lane][reg] =
            packh(__float2half_rn(Whh[(size_t)k * Hdim + n]),
                  __float2half_rn(Whh[(size_t)(k + 1) * Hdim + n]));
    }
}

// ---------------- phase A: tensor-core proj (fp16 A-single / B hi+lo, 2-pass) ----------------
#define PROJ_SMEM (3 * 16384)
__global__ void __launch_bounds__(256) proj_mma_kernel(
    const float* __restrict__ bu, const float* __restrict__ br, const float* __restrict__ bh)
{
    extern __shared__ char sm[];
    const uint32_t smb = (uint32_t)__cvta_generic_to_shared(sm);
    const int tid = threadIdx.x, wid = tid >> 5, lane = tid & 31;
    const int gid = lane >> 2, t4 = lane & 3;
    const int mw = wid & 3, nw = wid >> 2;
    const int rb = blockIdx.x * 128, cb = blockIdx.y * 128;
    const int gate = cb >> 10;
    const float* bias = (gate == 0) ? bu : (gate == 1 ? br : bh);

    const int lrowoff = ((lane >> 3) & 1) * 8 + (lane & 7);
    const int lkq = lane >> 4;
    const int lsw = (lane & 7) * 16;

    float acc[2][8][4];
#pragma unroll
    for (int mt = 0; mt < 2; mt++)
#pragma unroll
        for (int nt = 0; nt < 8; nt++)
#pragma unroll
            for (int i = 0; i < 4; i++) acc[mt][nt][i] = 0.f;

    auto load_chunk = [&](int st, int kc) {
#pragma unroll
        for (int q = 0; q < 4; q++) {
            int u = tid + q * 256;          // 0..1023
            int row = u >> 3, cu = u & 7;
            uint32_t dst = smb + st * 16384 + row * 128
                         + ((cu * 16) ^ ((row & 7) * 16));
            cp16(dst, g_xh + (size_t)(rb + row) * 256 + kc * 32 + cu * 4);
        }
        CP_COMMIT();
    };

    load_chunk(0, 0); load_chunk(1, 1); load_chunk(2, 2);
    for (int c = 0; c < 8; c++) {
        if (c <= 5)      CP_WAIT2();
        else if (c == 6) CP_WAIT1();
        else             CP_WAIT0();
        __syncthreads();
        const uint32_t base = smb + (c % 3) * 16384;
#pragma unroll
        for (int kl = 0; kl < 4; kl++) {
            const uint32_t bcol = (uint32_t)((kl * 32 + lkq * 16) ^ lsw);
            uint32_t Ah[2][4];
#pragma unroll
            for (int mt = 0; mt < 2; mt++) {
                const int mtile = mw * 2 + mt;
                ldsm4(Ah[mt], base + (uint32_t)((mtile * 16 + lrowoff) * 128) + bcol);
            }
#pragma unroll
            for (int nt = 0; nt < 8; nt++) {
                const int ntile = blockIdx.y * 16 + nw * 8 + nt;
                unsigned long long bhp = *(const unsigned long long*)&g_WpF2[0][ntile][c][lane][kl * 2];
                unsigned long long blp = *(const unsigned long long*)&g_WpF2[1][ntile][c][lane][kl * 2];
                const uint32_t bh0 = (uint32_t)bhp, bh1 = (uint32_t)(bhp >> 32);
                const uint32_t bl0 = (uint32_t)blp, bl1 = (uint32_t)(blp >> 32);
#pragma unroll
                for (int mt = 0; mt < 2; mt++) {
                    mma_hf(acc[mt][nt], Ah[mt], bh0, bh1);
                    mma_hf(acc[mt][nt], Ah[mt], bl0, bl1);
                }
            }
        }
        __syncthreads();
        if (c + 3 < 8) load_chunk(c % 3, c + 3);
    }

    float* gout = g_xproj + (size_t)gate * TBH;
#pragma unroll
    for (int nt = 0; nt < 8; nt++) {
        const int ncol = cb + nw * 64 + nt * 8 + t4 * 2;
        const int nn = ncol & (Hdim - 1);
        const float2 bv = *(const float2*)&bias[nn];
#pragma unroll
        for (int mt = 0; mt < 2; mt++) {
#pragma unroll
            for (int hf = 0; hf < 2; hf++) {
                const int m = rb + mw * 32 + mt * 16 + gid + hf * 8;
                const int t = m & (Tseq - 1), bb = m >> 9;
                float2 v;
                v.x = acc[mt][nt][hf * 2]     + bv.x;
                v.y = acc[mt][nt][hf * 2 + 1] + bv.y;
                *(float2*)&gout[((size_t)(t * Bsz + bb)) * Hdim + nn] = v;
            }
        }
    }
}

// ---------------- persistent recurrence: register-direct A, 16 warps ----------------
// warps: (ks 0-1) x (nh 0-1) x (mw 0-3). smem: Wzr 64KB | Whh 32KB | PART 8KB
#define REC_SMEM 106496
__global__ void __launch_bounds__(RNT, 1) gru_rec_kernel(float* __restrict__ out)
{
    extern __shared__ char sm[];
    const uint32_t smb = (uint32_t)__cvta_generic_to_shared(sm);
    float* PART = (float*)(sm + 98304);

    const int tid  = threadIdx.x, cta = blockIdx.x;
    const int wid  = tid >> 5, lane = tid & 31;
    const int gid  = lane >> 2, t4 = lane & 3;
    const int bhalf = cta & 1, bbase = bhalf * 64;
    const int ngrp  = cta >> 1;            // 0..63
    const int isR   = ngrp >= 32;

    const int mw = wid & 3, nh = (wid >> 2) & 1, ks = wid >> 3;
    const int rwid = nh * 4 + mw;          // 0..7, reduction slot

    // ---- preload this CTA's weight fragments into smem (once) ----
    {
        const char* s1 = (const char*)g_WzrS + (size_t)(ngrp * 4) * 16384;
#pragma unroll
        for (int q = 0; q < 8; q++)
            cp16(smb + (uint32_t)(tid + q * RNT) * 16, s1 + (size_t)(tid + q * RNT) * 16);
        const char* s2 = (const char*)g_WhhS + (size_t)(ngrp * 2) * 16384;
#pragma unroll
        for (int q = 0; q < 4; q++)
            cp16(smb + 65536 + (uint32_t)(tid + q * RNT) * 16, s2 + (size_t)(tid + q * RNT) * 16);
        CP_COMMIT();
        CP_WAIT0();
        __syncthreads();
    }

    const uint32_t* hFw  = &g_hF [bhalf][mw][0][0][0];   // [64][32][4]
    const uint32_t* rhFw = &g_rhF[bhalf][mw][0][0][0];

    for (int t = 0; t < Tseq; t++) {
        // ================= phase 1 : z / r (warp covers 2 nt = 16 cols) =================
        float acc[2][4];
#pragma unroll
        for (int nt = 0; nt < 2; nt++)
#pragma unroll
            for (int i = 0; i < 4; i++) acc[nt][i] = 0.f;

        const int Ncol0 = ngrp * 32 + nh * 16 + t4 * 2;     // + nt*8
        const int jj0 = isR ? (Ncol0 - Hdim) : Ncol0;
        float2 pxg[2][2], ph2[2][2];
        if (ks == 0) {
            const float* xg = g_xproj + (isR ? TBH : (size_t)0) + (size_t)t * BH;
#pragma unroll
            for (int nt = 0; nt < 2; nt++)
#pragma unroll
                for (int hf = 0; hf < 2; hf++) {
                    const int b = bbase + mw * 16 + gid + hf * 8;
                    pxg[nt][hf] = __ldcs((const float2*)(xg + (size_t)b * Hdim + jj0 + nt * 8));
                    if (isR) ph2[nt][hf] = __ldcg((const float2*)&g_h[(size_t)b * Hdim + jj0 + nt * 8]);
                }
        }

        // MMA loop, depth-4 register prefetch on the A-fragment LDG stream
        {
            uint4 Abuf[4];
#pragma unroll
            for (int p = 0; p < 4; p++)
                Abuf[p] = __ldcg((const uint4*)(hFw + (size_t)(p * 2 + ks) * 128 + lane * 4));
#pragma unroll 4
            for (int j = 0; j < 32; j++) {
                uint32_t A[4] = { Abuf[j & 3].x, Abuf[j & 3].y, Abuf[j & 3].z, Abuf[j & 3].w };
                if (j + 4 < 32)
                    Abuf[j & 3] = __ldcg((const uint4*)(hFw + (size_t)((j + 4) * 2 + ks) * 128 + lane * 4));
                const int kk = j * 2 + ks;
#pragma unroll
                for (int nt = 0; nt < 2; nt++) {
                    const uint2 Bv = *(const uint2*)(sm
                        + (size_t)((nh * 2 + nt) * 16384 + kk * 256 + lane * 8));
                    mma_hf(acc[nt], A, Bv.x, Bv.y);
                }
            }
        }

        // cross-k reduction (ks1 -> ks0)
        if (ks == 1) {
#pragma unroll
            for (int nt = 0; nt < 2; nt++)
#pragma unroll
                for (int i = 0; i < 4; i++)
                    PART[(rwid * 32 + lane) * 8 + nt * 4 + i] = acc[nt][i];
        }
        __syncthreads();
        if (ks == 0) {
#pragma unroll
            for (int nt = 0; nt < 2; nt++)
#pragma unroll
                for (int i = 0; i < 4; i++)
                    acc[nt][i] += PART[(rwid * 32 + lane) * 8 + nt * 4 + i];

            // phase1 epilogue
            if (!isR) {
#pragma unroll
                for (int nt = 0; nt < 2; nt++)
#pragma unroll
                    for (int hf = 0; hf < 2; hf++) {
                        const int b = bbase + mw * 16 + gid + hf * 8;
                        float2 zv;
                        zv.x = sigmoidf_(acc[nt][hf * 2]     + pxg[nt][hf].x);
                        zv.y = sigmoidf_(acc[nt][hf * 2 + 1] + pxg[nt][hf].y);
                        *(float2*)&g_z[(size_t)b * Hdim + Ncol0 + nt * 8] = zv;
                    }
            } else {
                // one coalesced uint4 fragment store per thread
                uint32_t v[4];
#pragma unroll
                for (int nt = 0; nt < 2; nt++)
#pragma unroll
                    for (int hf = 0; hf < 2; hf++) {
                        float r0 = sigmoidf_(acc[nt][hf * 2]     + pxg[nt][hf].x) * ph2[nt][hf].x;
                        float r1 = sigmoidf_(acc[nt][hf * 2 + 1] + pxg[nt][hf].y) * ph2[nt][hf].y;
                        v[hf + 2 * nt] = packh(__float2half_rn(r0), __float2half_rn(r1));
                    }
                const int kkq = (ngrp - 32) * 2 + nh;
                *(uint4*)&g_rhF[bhalf][mw][kkq][lane][0] = make_uint4(v[0], v[1], v[2], v[3]);
            }
        }

        // prefetch phase2 barrier-independent operands (xproj, h) before the barrier
        const int n0 = ngrp * 16 + nh * 8 + t4 * 2;
        float2 pxh[2], phv[2];
        if (ks == 0) {
            const float* xh = g_xproj + 2 * TBH + (size_t)t * BH;
#pragma unroll
            for (int hf = 0; hf < 2; hf++) {
                const int b = bbase + mw * 16 + gid + hf * 8;
                pxh[hf] = __ldcs((const float2*)(xh + (size_t)b * Hdim + n0));
                phv[hf] = __ldcg((const float2*)&g_h[(size_t)b * Hdim + n0]);
            }
        }
        grid_sync();

        // ================= phase 2 : candidate + update (warp covers nt = nh, 8 cols) =================
        float ac2[4] = { 0.f, 0.f, 0.f, 0.f };
        float2 pz2[2];
        if (ks == 0) {
#pragma unroll
            for (int hf = 0; hf < 2; hf++) {
                const int b = bbase + mw * 16 + gid + hf * 8;
                pz2[hf] = __ldcg((const float2*)&g_z[(size_t)b * Hdim + n0]);
            }
        }

        {
            uint4 Abuf[4];
#pragma unroll
            for (int p = 0; p < 4; p++)
                Abuf[p] = __ldcg((const uint4*)(rhFw + (size_t)(p * 2 + ks) * 128 + lane * 4));
#pragma unroll 4
            for (int j = 0; j < 32; j++) {
                uint32_t A[4] = { Abuf[j & 3].x, Abuf[j & 3].y, Abuf[j & 3].z, Abuf[j & 3].w };
                if (j + 4 < 32)
                    Abuf[j & 3] = __ldcg((const uint4*)(rhFw + (size_t)((j + 4) * 2 + ks) * 128 + lane * 4));
                const int kk = j * 2 + ks;
                const uint2 Bv = *(const uint2*)(sm
                    + (size_t)(65536 + nh * 16384 + kk * 256 + lane * 8));
                mma_hf(ac2, A, Bv.x, Bv.y);
            }
        }

        if (ks == 1) {
#pragma unroll
            for (int i = 0; i < 4; i++)
                PART[(rwid * 32 + lane) * 4 + i] = ac2[i];
        }
        __syncthreads();

        float hn[2][2];
        if (ks == 0) {
#pragma unroll
            for (int i = 0; i < 4; i++)
                ac2[i] += PART[(rwid * 32 + lane) * 4 + i];

            // phase2 epilogue: h update; uint2 fragment store (regs nh*2, nh*2+1)
            uint32_t v[2];
#pragma unroll
            for (int hf = 0; hf < 2; hf++) {
                const int b = bbase + mw * 16 + gid + hf * 8;
                float c0 = tanhf(ac2[hf * 2]     + pxh[hf].x);
                float c1 = tanhf(ac2[hf * 2 + 1] + pxh[hf].y);
                hn[hf][0] = phv[hf].x + pz2[hf].x * (c0 - phv[hf].x);
                hn[hf][1] = phv[hf].y + pz2[hf].y * (c1 - phv[hf].y);
                *(float2*)&g_h[(size_t)b * Hdim + n0] = make_float2(hn[hf][0], hn[hf][1]);
                v[hf] = packh(__float2half_rn(hn[hf][0]), __float2half_rn(hn[hf][1]));
            }
            *(uint2*)&g_hF[bhalf][mw][ngrp][lane][nh * 2] = make_uint2(v[0], v[1]);
        }
        __syncthreads();
        unsigned target = 0;
        if (tid == 0) target = grid_arrive();
        if (out && ks == 0) {
#pragma unroll
            for (int hf = 0; hf < 2; hf++) {
                const int b = bbase + mw * 16 + gid + hf * 8;
                *(float2*)&out[(size_t)t * BH + (size_t)b * Hdim + n0] =
                    make_float2(hn[hf][0], hn[hf][1]);
            }
        }
        if (tid == 0) grid_wait(target);
        __syncthreads();
    }
}

// ---------------- final hidden state ----------------
__global__ void hlast_kernel(float* __restrict__ dst) {
    int i = blockIdx.x * 256 + threadIdx.x;
    dst[i] = g_h[i];
}

// ---------------- launch ----------------
extern "C" void kernel_launch(void* const* d_in, const int* in_sizes, int n_in,
                              void* d_out, int out_size)
{
    (void)in_sizes; (void)n_in;
    const float* x   = (const float*)d_in[0];
    const float* h0  = (const float*)d_in[1];
    const float* Wiu = (const float*)d_in[2];
    const float* Whu = (const float*)d_in[3];
    const float* bu  = (const float*)d_in[4];
    const float* Wir = (const float*)d_in[5];
    const float* Whr = (const float*)d_in[6];
    const float* br  = (const float*)d_in[7];
    const float* Wih = (const float*)d_in[8];
    const float* Whh = (const float*)d_in[9];
    const float* bh  = (const float*)d_in[10];
    float* out = (float*)d_out;

    const bool write_seq  = ((size_t)out_size >= TBH);
    const bool write_last = ((size_t)out_size >= TBH + (size_t)Bsz * Hdim);

    cudaFuncSetAttribute(proj_mma_kernel,
                         cudaFuncAttributeMaxDynamicSharedMemorySize, PROJ_SMEM);
    cudaFuncSetAttribute(gru_rec_kernel,
                         cudaFuncAttributeMaxDynamicSharedMemorySize, REC_SMEM);

    setup_x_kernel<<<65536, 256>>>(x, h0);                          // launch 0
    setup_W_kernel<<<9216, 256>>>(Wiu, Wir, Wih, Whu, Whr, Whh);    // launch 1

    dim3 pg(Mrows / 128, 3072 / 128);   // 512 x 24
    proj_mma_kernel<<<pg, 256, PROJ_SMEM>>>(bu, br, bh);            // launch 2

    gru_rec_kernel<<<NC, RNT, REC_SMEM>>>(write_seq ? out : nullptr); // launch 3 (ncu slot)

    if (write_last)        hlast_kernel<<<BH / 256, 256>>>(out + TBH);
    else if (!write_seq)   hlast_kernel<<<BH / 256, 256>>>(out);
}

// round 17
// speedup vs baseline: 1.0821x; 1.0524x over previous
#include <cuda_runtime.h>
#include <cuda_fp16.h>
#include <cstdint>

#define Bsz  128
#define Tseq 512
#define Din  512
#define Hdim 1024
#define BH   (Bsz * Hdim)
#define TBH  ((size_t)Tseq * (size_t)Bsz * (size_t)Hdim)
#define NC   128
#define NT   256
#define Mrows 65536            // B*T

// ---------------- static device scratch ----------------
__device__ float g_xproj[3ULL * 512ULL * 128ULL * 1024ULL]; // (gate, t, b, h)
__device__ float g_h[BH];                 // h fp32, [b][k]
__device__ float g_z[BH];                 // z gate fp32, [b][n]
__device__ uint32_t g_hfp [BH / 2];       // h  fp16 packed pairs [b][k/2]
__device__ uint32_t g_rhfp[BH / 2];       // r*h fp16 packed pairs
__device__ uint32_t g_xh[(size_t)Mrows * (Din / 2)];   // x fp16 packed pairs (proj A)
__device__ uint32_t g_WzrS[256][64][32][2];     // rec B-frags fp16 single
__device__ uint32_t g_WhhS[128][64][32][2];
__device__ uint32_t g_WpF2[2][384][8][32][8];   // proj B-frags fp16 hi/lo
__device__ unsigned int g_bar = 0;

// ---------------- helpers ----------------
__device__ __forceinline__ float sigmoidf_(float x) { return 1.0f / (1.0f + __expf(-x)); }

__device__ __forceinline__ void hsplit(float v, __half& hi, __half& lo) {
    hi = __float2half_rn(v);
    lo = __float2half_rn(v - __half2float(hi));
}
__device__ __forceinline__ uint32_t packh(__half a, __half b) {
    __half2 h2 = __halves2half2(a, b);
    return *(uint32_t*)&h2;
}

__device__ __forceinline__ void cp16(uint32_t s, const void* g) {
    asm volatile("cp.async.cg.shared.global [%0], [%1], 16;" :: "r"(s), "l"(g));
}
#define CP_COMMIT() asm volatile("cp.async.commit_group;")
#define CP_WAIT0()  asm volatile("cp.async.wait_group 0;")
#define CP_WAIT1()  asm volatile("cp.async.wait_group 1;")
#define CP_WAIT2()  asm volatile("cp.async.wait_group 2;")
#define CP_WAIT3()  asm volatile("cp.async.wait_group 3;")

__device__ __forceinline__ unsigned grid_arrive() {
    unsigned old;
    asm volatile("atom.release.gpu.global.add.u32 %0, [%1], 1;"
                 : "=r"(old) : "l"(&g_bar) : "memory");
    return (old / NC + 1u) * NC;
}
__device__ __forceinline__ void grid_wait(unsigned target) {
    unsigned v;
    do {
        asm volatile("ld.acquire.gpu.global.u32 %0, [%1];"
                     : "=r"(v) : "l"(&g_bar) : "memory");
    } while (v < target);
}
__device__ __forceinline__ void grid_sync() {
    __syncthreads();
    if (threadIdx.x == 0) grid_wait(grid_arrive());
    __syncthreads();
}

__device__ __forceinline__ void ldsm4(uint32_t (&r)[4], uint32_t a) {
    asm volatile("ldmatrix.sync.aligned.m8n8.x4.shared.b16 {%0,%1,%2,%3}, [%4];"
                 : "=r"(r[0]), "=r"(r[1]), "=r"(r[2]), "=r"(r[3]) : "r"(a));
}
__device__ __forceinline__ void mma_hf(float (&d)[4], const uint32_t (&a)[4],
                                       uint32_t b0, uint32_t b1) {
    asm volatile(
        "mma.sync.aligned.m16n8k16.row.col.f32.f16.f16.f32 "
        "{%0,%1,%2,%3}, {%4,%5,%6,%7}, {%8,%9}, {%0,%1,%2,%3};"
        : "+f"(d[0]), "+f"(d[1]), "+f"(d[2]), "+f"(d[3])
        : "r"(a[0]), "r"(a[1]), "r"(a[2]), "r"(a[3]), "r"(b0), "r"(b1));
}

// ---------------- merged setup kernels (2 launches) ----------------
__global__ void setup_x_kernel(const float* __restrict__ x, const float* __restrict__ h0) {
    size_t i = (size_t)blockIdx.x * 256 + threadIdx.x;   // Mrows*Din/2
    float2 v = *(const float2*)&x[i * 2];
    g_xh[i] = packh(__float2half_rn(v.x), __float2half_rn(v.y));
    if (i < BH / 2) {
        int b = (int)(i >> 9), kp = (int)(i & 511);
        float2 h2 = *(const float2*)&h0[(size_t)b * Hdim + kp * 2];
        *(float2*)&g_h[(size_t)b * Hdim + kp * 2] = h2;
        g_hfp[(size_t)b * 512 + kp] = packh(__float2half_rn(h2.x), __float2half_rn(h2.y));
    }
}

__global__ void setup_W_kernel(const float* __restrict__ Wiu, const float* __restrict__ Wir,
                               const float* __restrict__ Wih, const float* __restrict__ Whu,
                               const float* __restrict__ Whr, const float* __restrict__ Whh) {
    int i = blockIdx.x * 256 + threadIdx.x;
    if (i < 786432) {                                   // proj B-frags (hi/lo)
        int e = i & 7, lane = (i >> 3) & 31, kc = (i >> 8) & 7, nt = i >> 11;
        int kl = e >> 1, reg = e & 1;
        int n = nt * 8 + (lane >> 2);
        int gate = n >> 10, nn = n & (Hdim - 1);
        const float* W = (gate == 0) ? Wiu : (gate == 1 ? Wir : Wih);
        int k = kc * 64 + kl * 16 + reg * 8 + (lane & 3) * 2;
        float v0 = W[(size_t)k * Hdim + nn];
        float v1 = W[(size_t)(k + 1) * Hdim + nn];
        __half h0a, l0a, h1a, l1a;
        hsplit(v0, h0a, l0a); hsplit(v1, h1a, l1a);
        g_WpF2[0][nt][kc][lane][e] = packh(h0a, h1a);
        g_WpF2[1][nt][kc][lane][e] = packh(l0a, l1a);
    } else if (i < 786432 + 1048576) {                  // Wzr single fp16
        int u = i - 786432;
        int reg = u & 1, lane = (u >> 1) & 31, k16 = (u >> 6) & 63, nt = u >> 12;
        int n = nt * 8 + (lane >> 2);
        int k = k16 * 16 + reg * 8 + (lane & 3) * 2;
        const float* W = (n < Hdim) ? Whu : Whr;
        int nn = n & (Hdim - 1);
        g_WzrS[nt][k16][lane][reg] =
            packh(__float2half_rn(W[(size_t)k * Hdim + nn]),
                  __float2half_rn(W[(size_t)(k + 1) * Hdim + nn]));
    } else {                                            // Whh single fp16
        int u = i - 786432 - 1048576;
        int reg = u & 1, lane = (u >> 1) & 31, k16 = (u >> 6) & 63, nt = u >> 12;
        int n = nt * 8 + (lane >> 2);
        int k = k16 * 16 + reg * 8 + (lane & 3) * 2;
        g_WhhS[nt][k16][lane][reg] =
            packh(__float2half_rn(Whh[(size_t)k * Hdim + n]),
                  __float2half_rn(Whh[(size_t)(k + 1) * Hdim + n]));
    }
}

// ---------------- phase A: tensor-core proj (fp16 A-single / B hi+lo, 2-pass) ----------------
#define PROJ_SMEM (3 * 16384)
__global__ void __launch_bounds__(256) proj_mma_kernel(
    const float* __restrict__ bu, const float* __restrict__ br, const float* __restrict__ bh)
{
    extern __shared__ char sm[];
    const uint32_t smb = (uint32_t)__cvta_generic_to_shared(sm);
    const int tid = threadIdx.x, wid = tid >> 5, lane = tid & 31;
    const int gid = lane >> 2, t4 = lane & 3;
    const int mw = wid & 3, nw = wid >> 2;
    const int rb = blockIdx.x * 128, cb = blockIdx.y * 128;
    const int gate = cb >> 10;
    const float* bias = (gate == 0) ? bu : (gate == 1 ? br : bh);

    const int lrowoff = ((lane >> 3) & 1) * 8 + (lane & 7);
    const int lkq = lane >> 4;
    const int lsw = (lane & 7) * 16;

    float acc[2][8][4];
#pragma unroll
    for (int mt = 0; mt < 2; mt++)
#pragma unroll
        for (int nt = 0; nt < 8; nt++)
#pragma unroll
            for (int i = 0; i < 4; i++) acc[mt][nt][i] = 0.f;

    auto load_chunk = [&](int st, int kc) {
#pragma unroll
        for (int q = 0; q < 4; q++) {
            int u = tid + q * 256;          // 0..1023
            int row = u >> 3, cu = u & 7;
            uint32_t dst = smb + st * 16384 + row * 128
                         + ((cu * 16) ^ ((row & 7) * 16));
            cp16(dst, g_xh + (size_t)(rb + row) * 256 + kc * 32 + cu * 4);
        }
        CP_COMMIT();
    };

    load_chunk(0, 0); load_chunk(1, 1); load_chunk(2, 2);
    for (int c = 0; c < 8; c++) {
        if (c <= 5)      CP_WAIT2();
        else if (c == 6) CP_WAIT1();
        else             CP_WAIT0();
        __syncthreads();
        const uint32_t base = smb + (c % 3) * 16384;
#pragma unroll
        for (int kl = 0; kl < 4; kl++) {
            const uint32_t bcol = (uint32_t)((kl * 32 + lkq * 16) ^ lsw);
            uint32_t Ah[2][4];
#pragma unroll
            for (int mt = 0; mt < 2; mt++) {
                const int mtile = mw * 2 + mt;
                ldsm4(Ah[mt], base + (uint32_t)((mtile * 16 + lrowoff) * 128) + bcol);
            }
#pragma unroll
            for (int nt = 0; nt < 8; nt++) {
                const int ntile = blockIdx.y * 16 + nw * 8 + nt;
                unsigned long long bhp = *(const unsigned long long*)&g_WpF2[0][ntile][c][lane][kl * 2];
                unsigned long long blp = *(const unsigned long long*)&g_WpF2[1][ntile][c][lane][kl * 2];
                const uint32_t bh0 = (uint32_t)bhp, bh1 = (uint32_t)(bhp >> 32);
                const uint32_t bl0 = (uint32_t)blp, bl1 = (uint32_t)(blp >> 32);
#pragma unroll
                for (int mt = 0; mt < 2; mt++) {
                    mma_hf(acc[mt][nt], Ah[mt], bh0, bh1);
                    mma_hf(acc[mt][nt], Ah[mt], bl0, bl1);
                }
            }
        }
        __syncthreads();
        if (c + 3 < 8) load_chunk(c % 3, c + 3);
    }

    float* gout = g_xproj + (size_t)gate * TBH;
#pragma unroll
    for (int nt = 0; nt < 8; nt++) {
        const int ncol = cb + nw * 64 + nt * 8 + t4 * 2;
        const int nn = ncol & (Hdim - 1);
        const float2 bv = *(const float2*)&bias[nn];
#pragma unroll
        for (int mt = 0; mt < 2; mt++) {
#pragma unroll
            for (int hf = 0; hf < 2; hf++) {
                const int m = rb + mw * 32 + mt * 16 + gid + hf * 8;
                const int t = m & (Tseq - 1), bb = m >> 9;
                float2 v;
                v.x = acc[mt][nt][hf * 2]     + bv.x;
                v.y = acc[mt][nt][hf * 2 + 1] + bv.y;
                *(float2*)&gout[((size_t)(t * Bsz + bb)) * Hdim + nn] = v;
            }
        }
    }
}

// ---------------- persistent recurrence: A-resident phases, fp16 single (R11 config) ----------------
// smem: [0,65536) Wzr frags (4 ntiles x 16KB) | [65536,98304) Whh frags (2 x 16KB)
//       [98304, 229376) A panel: 16 sub-blocks of (64 rows x 64 k fp16, SW128) = 128 KB
#define REC_SMEM 229376
__global__ void __launch_bounds__(NT, 1) gru_rec_kernel(float* __restrict__ out)
{
    extern __shared__ char sm[];
    const uint32_t smb = (uint32_t)__cvta_generic_to_shared(sm);
    const uint32_t abase = smb + 98304;

    const int tid  = threadIdx.x, cta = blockIdx.x;
    const int wid  = tid >> 5, lane = tid & 31;
    const int gid  = lane >> 2, t4 = lane & 3;
    const int bhalf = cta & 1, bbase = bhalf * 64;
    const int ngrp  = cta >> 1;            // 0..63
    const int isR   = ngrp >= 32;

    // warp tiling: 4 mtiles (mw) x 2 n-halves (nh)
    const int mw = wid & 3, nh = wid >> 2;

    const int lrowoff = ((lane >> 3) & 1) * 8 + (lane & 7);
    const int lkq  = lane >> 4;
    const int lsw  = (lane & 7) * 16;

    // ---- preload this CTA's weight fragments into smem (once) ----
    {
        const char* s1 = (const char*)g_WzrS + (size_t)(ngrp * 4) * 16384;
#pragma unroll
        for (int q = 0; q < 16; q++)
            cp16(smb + (uint32_t)(tid + q * NT) * 16, s1 + (size_t)(tid + q * NT) * 16);
        const char* s2 = (const char*)g_WhhS + (size_t)(ngrp * 2) * 16384;
#pragma unroll
        for (int q = 0; q < 8; q++)
            cp16(smb + 65536 + (uint32_t)(tid + q * NT) * 16, s2 + (size_t)(tid + q * NT) * 16);
        CP_COMMIT();
        CP_WAIT0();
        __syncthreads();
    }

    // Issue the FULL 128 KB A panel in 4 commit groups (group g = k range [g*256, g*256+256))
    auto load_A = [&](const uint32_t* s) {
#pragma unroll
        for (int g = 0; g < 4; g++) {
#pragma unroll
            for (int q = 0; q < 8; q++) {
                int u = tid + q * NT;            // 0..2047
                int sub = u >> 9, rem = u & 511;
                int row = rem >> 3, cu = rem & 7;
                uint32_t dst = abase + (uint32_t)(g * 4 + sub) * 8192 + row * 128
                             + ((cu * 16) ^ ((row & 7) * 16));
                cp16(dst, s + (size_t)(bbase + row) * 512 + g * 128 + sub * 32 + cu * 4);
            }
            CP_COMMIT();
        }
    };

    for (int t = 0; t < Tseq; t++) {
        // ================= phase 1 : z / r =================
        float acc[2][4];
#pragma unroll
        for (int nt = 0; nt < 2; nt++)
#pragma unroll
            for (int i = 0; i < 4; i++) acc[nt][i] = 0.f;

        load_A(g_hfp);

        // prefetch phase1 epilogue operands (latency hidden under MMA loop)
        const int Ncol0 = ngrp * 32 + nh * 16 + t4 * 2;     // + nt*8
        const int jj0 = isR ? (Ncol0 - Hdim) : Ncol0;
        const float* xg = g_xproj + (isR ? TBH : (size_t)0) + (size_t)t * BH;
        float2 pxg[2][2], ph2[2][2];
#pragma unroll
        for (int nt = 0; nt < 2; nt++)
#pragma unroll
            for (int hf = 0; hf < 2; hf++) {
                const int b = bbase + mw * 16 + gid + hf * 8;
                pxg[nt][hf] = __ldcs((const float2*)(xg + (size_t)b * Hdim + jj0 + nt * 8));
                if (isR) ph2[nt][hf] = __ldcg((const float2*)&g_h[(size_t)b * Hdim + jj0 + nt * 8]);
            }

#pragma unroll
        for (int g = 0; g < 4; g++) {
            if (g == 0)      CP_WAIT3();
            else if (g == 1) CP_WAIT2();
            else if (g == 2) CP_WAIT1();
            else             CP_WAIT0();
            __syncthreads();
#pragma unroll
            for (int kl = 0; kl < 16; kl++) {
                const int kk = g * 16 + kl;
                const uint32_t asub = abase + (uint32_t)(kk >> 2) * 8192;
                const uint32_t bcol = (uint32_t)(((kk & 3) * 32 + lkq * 16) ^ lsw);
                uint32_t Ah[4];
                ldsm4(Ah, asub + (uint32_t)((mw * 16 + lrowoff) * 128) + bcol);
#pragma unroll
                for (int nt = 0; nt < 2; nt++) {
                    const uint2 Bv = *(const uint2*)(sm
                        + (size_t)((nh * 2 + nt) * 16384 + kk * 256 + lane * 8));
                    mma_hf(acc[nt], Ah, Bv.x, Bv.y);
                }
            }
        }

        // phase1 epilogue
#pragma unroll
        for (int nt = 0; nt < 2; nt++) {
#pragma unroll
            for (int hf = 0; hf < 2; hf++) {
                const int b = bbase + mw * 16 + gid + hf * 8;
                const float dx = acc[nt][hf * 2], dy = acc[nt][hf * 2 + 1];
                if (!isR) {
                    float2 zv;
                    zv.x = sigmoidf_(dx + pxg[nt][hf].x);
                    zv.y = sigmoidf_(dy + pxg[nt][hf].y);
                    *(float2*)&g_z[(size_t)b * Hdim + Ncol0 + nt * 8] = zv;
                } else {
                    const int j = jj0 + nt * 8;
                    float r0 = sigmoidf_(dx + pxg[nt][hf].x) * ph2[nt][hf].x;
                    float r1 = sigmoidf_(dy + pxg[nt][hf].y) * ph2[nt][hf].y;
                    g_rhfp[(size_t)b * 512 + (j >> 1)] =
                        packh(__float2half_rn(r0), __float2half_rn(r1));
                }
            }
        }

        // prefetch phase-2 barrier-independent operands (xproj const; g_h stable through phase1)
        const int n = ngrp * 16 + nh * 8 + t4 * 2;
        const float* xh = g_xproj + 2 * TBH + (size_t)t * BH;
        float2 pxh[2], phv[2];
#pragma unroll
        for (int hf = 0; hf < 2; hf++) {
            const int b = bbase + mw * 16 + gid + hf * 8;
            pxh[hf] = __ldcs((const float2*)(xh + (size_t)b * Hdim + n));
            phv[hf] = __ldcg((const float2*)&g_h[(size_t)b * Hdim + n]);
        }
        grid_sync();

        // ================= phase 2 : candidate + update =================
        float ac2[4] = { 0.f, 0.f, 0.f, 0.f };
        load_A(g_rhfp);

        float2 pz2[2];
#pragma unroll
        for (int hf = 0; hf < 2; hf++) {
            const int b = bbase + mw * 16 + gid + hf * 8;
            pz2[hf] = __ldcg((const float2*)&g_z[(size_t)b * Hdim + n]);
        }

#pragma unroll
        for (int g = 0; g < 4; g++) {
            if (g == 0)      CP_WAIT3();
            else if (g == 1) CP_WAIT2();
            else if (g == 2) CP_WAIT1();
            else             CP_WAIT0();
            __syncthreads();
#pragma unroll
            for (int kl = 0; kl < 16; kl++) {
                const int kk = g * 16 + kl;
                const uint32_t asub = abase + (uint32_t)(kk >> 2) * 8192;
                const uint32_t bcol = (uint32_t)(((kk & 3) * 32 + lkq * 16) ^ lsw);
                uint32_t Ah[4];
                ldsm4(Ah, asub + (uint32_t)((mw * 16 + lrowoff) * 128) + bcol);
                const uint2 Bv = *(const uint2*)(sm
                    + (size_t)(65536 + nh * 16384 + kk * 256 + lane * 8));
                mma_hf(ac2, Ah, Bv.x, Bv.y);
            }
        }

        // phase2 epilogue: write h state, arrive, then out-store overlaps the barrier wait
        float hn[2][2];
#pragma unroll
        for (int hf = 0; hf < 2; hf++) {
            const int b = bbase + mw * 16 + gid + hf * 8;
            float c0 = tanhf(ac2[hf * 2]     + pxh[hf].x);
            float c1 = tanhf(ac2[hf * 2 + 1] + pxh[hf].y);
            hn[hf][0] = phv[hf].x + pz2[hf].x * (c0 - phv[hf].x);
            hn[hf][1] = phv[hf].y + pz2[hf].y * (c1 - phv[hf].y);
            *(float2*)&g_h[(size_t)b * Hdim + n] = make_float2(hn[hf][0], hn[hf][1]);
            g_hfp[(size_t)b * 512 + (n >> 1)] =
                packh(__float2half_rn(hn[hf][0]), __float2half_rn(hn[hf][1]));
        }
        __syncthreads();
        unsigned target = 0;
        if (tid == 0) target = grid_arrive();
        if (out) {
#pragma unroll
            for (int hf = 0; hf < 2; hf++) {
                const int b = bbase + mw * 16 + gid + hf * 8;
                *(float2*)&out[(size_t)t * BH + (size_t)b * Hdim + n] =
                    make_float2(hn[hf][0], hn[hf][1]);
            }
        }
        if (tid == 0) grid_wait(target);
        __syncthreads();
    }
}

// ---------------- final hidden state ----------------
__global__ void hlast_kernel(float* __restrict__ dst) {
    int i = blockIdx.x * 256 + threadIdx.x;
    dst[i] = g_h[i];
}

// ---------------- launch ----------------
extern "C" void kernel_launch(void* const* d_in, const int* in_sizes, int n_in,
                              void* d_out, int out_size)
{
    (void)in_sizes; (void)n_in;
    const float* x   = (const float*)d_in[0];
    const float* h0  = (const float*)d_in[1];
    const float* Wiu = (const float*)d_in[2];
    const float* Whu = (const float*)d_in[3];
    const float* bu  = (const float*)d_in[4];
    const float* Wir = (const float*)d_in[5];
    const float* Whr = (const float*)d_in[6];
    const float* br  = (const float*)d_in[7];
    const float* Wih = (const float*)d_in[8];
    const float* Whh = (const float*)d_in[9];
    const float* bh  = (const float*)d_in[10];
    float* out = (float*)d_out;

    const bool write_seq  = ((size_t)out_size >= TBH);
    const bool write_last = ((size_t)out_size >= TBH + (size_t)Bsz * Hdim);

    cudaFuncSetAttribute(proj_mma_kernel,
                         cudaFuncAttributeMaxDynamicSharedMemorySize, PROJ_SMEM);
    cudaFuncSetAttribute(gru_rec_kernel,
                         cudaFuncAttributeMaxDynamicSharedMemorySize, REC_SMEM);

    setup_x_kernel<<<65536, 256>>>(x, h0);                          // launch 0
    setup_W_kernel<<<9216, 256>>>(Wiu, Wir, Wih, Whu, Whr, Whh);    // launch 1

    dim3 pg(Mrows / 128, 3072 / 128);   // 512 x 24
    proj_mma_kernel<<<pg, 256, PROJ_SMEM>>>(bu, br, bh);            // launch 2

    gru_rec_kernel<<<NC, NT, REC_SMEM>>>(write_seq ? out : nullptr); // launch 3 (ncu slot)

    if (write_last)        hlast_kernel<<<BH / 256, 256>>>(out + TBH);
    else if (!write_seq)   hlast_kernel<<<BH / 256, 256>>>(out);
}